// round 11
// baseline (speedup 1.0000x reference)
#include <cuda_runtime.h>
#include <cuda_bf16.h>
#include <math.h>

// Problem constants
#define K_ 128
#define J_ 4
#define N_ 64
#define R_ 32
#define T_ 32
#define S_ 256
#define A_ 4
#define D_ 64
#define Z_ (K_*J_)   // 512
#define TM1 (T_-1)   // 31
#define RP1 (R_+1)   // 33

// Output segment offsets (floats)
#define O0 0u
#define O1 4224u
#define O2 8448u
#define O3 12672u
#define O4 16896u
#define O5 287232u
#define O6 291200u
#define O7 295168u
#define O8 549120u
#define O9 4612352u
#define O10 4612480u
#define O11 4612608u

#define LOG10F 2.302585092994045684f
#define LOG4F  1.3862943611198906f

// ---------------- scratch ----------------
__device__ float g_ckept[K_*T_];
__device__ float g_llnew[Z_];
__device__ float g_P1[Z_*16];
__device__ float g_P2[Z_*16];
__device__ int4  g_selinfo[K_];   // {gk, i1, i2, zs}

__device__ __forceinline__ float f_logdf(const float* logdf, int l) {
    int di = 2*l - 3;
    di = max(0, min(2*N_ - 1, di));
    return logdf[di];
}

// ---------------- Kernel 1: kA halves [0,2K) + kB candidates [2K,2K+Z) -------
// kA: one warp = TWO independent lf rows (2x ILP), no smem, no syncthreads.
// kB: head dots parallel across warps 0-4; warp 0 does Q/softmax/expm.
__global__ void __launch_bounds__(256, 6) k1(
        const int* __restrict__ indexes,
        const int* __restrict__ lc, const float* __restrict__ embt,
        const float* __restrict__ lf, const float* __restrict__ Wstat,
        const int* __restrict__ idx1a, const int* __restrict__ idx2a,
        const float* __restrict__ br1, const float* __restrict__ br2,
        const float* __restrict__ embJ, const float* __restrict__ Wq) {
    int tid = threadIdx.x;
    int warp = tid >> 5, lane = tid & 31;

    if (blockIdx.x < 2*K_) {
        // ----- kA half: rows h*16 + warp and h*16 + warp + 8 -----
        int k = blockIdx.x >> 1, h = blockIdx.x & 1;
        int gk = indexes[k];
        int tA = h*16 + warp;
        int tB = tA + 8;

        const float2* eA2 = (const float2*)(embt + (size_t)(gk*T_ + tA)*D_);
        const float2* eB2 = (const float2*)(embt + (size_t)(gk*T_ + tB)*D_);
        float2 ea = eA2[lane];
        float2 eb = eB2[lane];
        const float4* w4 = (const float4*)Wstat;
        float4 wa = w4[2*lane], wb = w4[2*lane + 1];
        float a0 = ea.x*wa.x + ea.y*wb.x;
        float a1 = ea.x*wa.y + ea.y*wb.y;
        float a2 = ea.x*wa.z + ea.y*wb.z;
        float a3 = ea.x*wa.w + ea.y*wb.w;
        float b0 = eb.x*wa.x + eb.y*wb.x;
        float b1 = eb.x*wa.y + eb.y*wb.y;
        float b2 = eb.x*wa.z + eb.y*wb.z;
        float b3 = eb.x*wa.w + eb.y*wb.w;
        #pragma unroll
        for (int off = 16; off; off >>= 1) {
            a0 += __shfl_xor_sync(0xffffffffu, a0, off);
            a1 += __shfl_xor_sync(0xffffffffu, a1, off);
            a2 += __shfl_xor_sync(0xffffffffu, a2, off);
            a3 += __shfl_xor_sync(0xffffffffu, a3, off);
            b0 += __shfl_xor_sync(0xffffffffu, b0, off);
            b1 += __shfl_xor_sync(0xffffffffu, b1, off);
            b2 += __shfl_xor_sync(0xffffffffu, b2, off);
            b3 += __shfl_xor_sync(0xffffffffu, b3, off);
        }
        // softmax row A
        float mA = fmaxf(fmaxf(a0, a1), fmaxf(a2, a3));
        float pA0 = __expf(a0 - mA), pA1 = __expf(a1 - mA);
        float pA2 = __expf(a2 - mA), pA3 = __expf(a3 - mA);
        float invA = 1.f / (pA0 + pA1 + pA2 + pA3);
        pA0 *= invA; pA1 *= invA; pA2 *= invA; pA3 *= invA;
        // softmax row B
        float mB = fmaxf(fmaxf(b0, b1), fmaxf(b2, b3));
        float pB0 = __expf(b0 - mB), pB1 = __expf(b1 - mB);
        float pB2 = __expf(b2 - mB), pB3 = __expf(b3 - mB);
        float invB = 1.f / (pB0 + pB1 + pB2 + pB3);
        pB0 *= invB; pB1 *= invB; pB2 *= invB; pB3 *= invB;

        const float4* rowA = (const float4*)(lf + (size_t)(gk*T_ + tA)*S_*A_);
        const float4* rowB = (const float4*)(lf + (size_t)(gk*T_ + tB)*S_*A_);
        float prodA0 = 1.f, prodA1v = 1.f, prodB0 = 1.f, prodB1v = 1.f;
        #pragma unroll
        for (int g = 0; g < 4; g++) {
            // batch 4 independent loads (2 per row)
            float4 vA0 = rowA[lane + 32*(2*g)];
            float4 vA1 = rowA[lane + 32*(2*g + 1)];
            float4 vB0 = rowB[lane + 32*(2*g)];
            float4 vB1 = rowB[lane + 32*(2*g + 1)];
            float dA0 = pA0*__expf(vA0.x) + pA1*__expf(vA0.y)
                      + pA2*__expf(vA0.z) + pA3*__expf(vA0.w);
            float dA1 = pA0*__expf(vA1.x) + pA1*__expf(vA1.y)
                      + pA2*__expf(vA1.z) + pA3*__expf(vA1.w);
            float dB0 = pB0*__expf(vB0.x) + pB1*__expf(vB0.y)
                      + pB2*__expf(vB0.z) + pB3*__expf(vB0.w);
            float dB1 = pB0*__expf(vB1.x) + pB1*__expf(vB1.y)
                      + pB2*__expf(vB1.z) + pB3*__expf(vB1.w);
            prodA0 *= dA0; prodA1v *= dA1;
            prodB0 *= dB0; prodB1v *= dB1;
        }
        float accA = __logf(prodA0 * prodA1v);
        float accB = __logf(prodB0 * prodB1v);
        #pragma unroll
        for (int off = 16; off; off >>= 1) {
            accA += __shfl_xor_sync(0xffffffffu, accA, off);
            accB += __shfl_xor_sync(0xffffffffu, accB, off);
        }
        if (lane == 0) {
            g_ckept[k*T_ + tA] = accA;
            g_ckept[k*T_ + tB] = accB;
        }
    } else {
        // ----- kB candidate z -----
        int z = blockIdx.x - 2*K_;
        int k = z / J_;
        int gk = indexes[k];
        __shared__ float slog[20];
        __shared__ float sP1[16], sP2[16], sstat[4];
        __shared__ float s_red[8];

        int i1 = idx1a[z], i2 = idx2a[z];
        float bb1 = br1[z], bb2 = br2[z];

        const float4* r1 = (const float4*)(lf + (size_t)(gk*T_ + i1)*S_*A_);
        const float4* r2 = (const float4*)(lf + (size_t)(gk*T_ + i2)*S_*A_);
        float4 w1 = r1[tid], w2 = r2[tid];
        float e10=__expf(w1.x), e11=__expf(w1.y), e12=__expf(w1.z), e13=__expf(w1.w);
        float e20=__expf(w2.x), e21=__expf(w2.y), e22=__expf(w2.z), e23=__expf(w2.w);

        // head: warps 0-4 compute logits 4w..4w+3 (lane covers dims 2l, 2l+1)
        if (warp < 5) {
            const float2* emb2 = (const float2*)(embJ + (size_t)z*D_);
            float2 e = emb2[lane];
            float l0, l1, l2, l3;
            if (warp < 4) {
                int col = 4*warp;
                const float* Wq0 = Wq + (2*lane)*16 + col;
                const float* Wq1 = Wq + (2*lane + 1)*16 + col;
                l0 = e.x*Wq0[0] + e.y*Wq1[0];
                l1 = e.x*Wq0[1] + e.y*Wq1[1];
                l2 = e.x*Wq0[2] + e.y*Wq1[2];
                l3 = e.x*Wq0[3] + e.y*Wq1[3];
            } else {
                const float4* ws4 = (const float4*)Wstat;
                float4 wsa = ws4[2*lane], wsb = ws4[2*lane + 1];
                l0 = e.x*wsa.x + e.y*wsb.x;
                l1 = e.x*wsa.y + e.y*wsb.y;
                l2 = e.x*wsa.z + e.y*wsb.z;
                l3 = e.x*wsa.w + e.y*wsb.w;
            }
            #pragma unroll
            for (int off = 16; off; off >>= 1) {
                l0 += __shfl_xor_sync(0xffffffffu, l0, off);
                l1 += __shfl_xor_sync(0xffffffffu, l1, off);
                l2 += __shfl_xor_sync(0xffffffffu, l2, off);
                l3 += __shfl_xor_sync(0xffffffffu, l3, off);
            }
            if (lane == 0) {
                slog[4*warp + 0] = l0;
                slog[4*warp + 1] = l1;
                slog[4*warp + 2] = l2;
                slog[4*warp + 3] = l3;
            }
        }
        __syncthreads();

        if (warp == 0) {
            float logit = (lane < 20) ? slog[lane] : 0.f;
            {   // stat softmax (lanes 16..19); all lanes execute shuffles
                float mm = fmaxf(logit, __shfl_xor_sync(0xffffffffu, logit, 1));
                mm = fmaxf(mm, __shfl_xor_sync(0xffffffffu, mm, 2));
                float ex = __expf(logit - mm);
                float ttl = ex + __shfl_xor_sync(0xffffffffu, ex, 1);
                ttl += __shfl_xor_sync(0xffffffffu, ttl, 2);
                if (lane >= 16 && lane < 20) sstat[lane - 16] = ex / ttl;
            }
            int e = lane & 15, r = e >> 2, c = e & 3;
            float qoff = 0.f;
            if (lane < 16) {
                float x = logit;
                float sp = fmaxf(x, 0.f) + log1pf(__expf(-fabsf(x)));
                qoff = (r == c) ? 0.f : sp;
            }
            float s1 = qoff + __shfl_xor_sync(0xffffffffu, qoff, 1);
            float rs = s1 + __shfl_xor_sync(0xffffffffu, s1, 2);
            float Qown = (r == c) ? -rs : qoff;
            float Qe = __shfl_sync(0xffffffffu, Qown, lane & 15);

            // expm: lanes 0-15 -> P1, lanes 16-31 -> P2; fixed s=3, Taylor-7 (R9 variant)
            int base = lane & 16;
            float bsc = ((lane < 16) ? bb1 : bb2) * 0.125f;
            float Av = Qe * bsc;
            float Ev = Av + ((r == c) ? 1.f : 0.f);
            float Tm = Av;
            #pragma unroll
            for (int n = 2; n <= 7; n++) {
                float s = 0.f;
                #pragma unroll
                for (int j = 0; j < 4; j++) {
                    float trj = __shfl_sync(0xffffffffu, Tm, base + (r<<2) + j);
                    float ajc = __shfl_sync(0xffffffffu, Av, base + (j<<2) + c);
                    s += trj * ajc;
                }
                Tm = s * (1.f / (float)n);
                Ev += Tm;
            }
            #pragma unroll
            for (int qq = 0; qq < 3; qq++) {
                float s = 0.f;
                #pragma unroll
                for (int j = 0; j < 4; j++) {
                    float erj = __shfl_sync(0xffffffffu, Ev, base + (r<<2) + j);
                    float ejc = __shfl_sync(0xffffffffu, Ev, base + (j<<2) + c);
                    s += erj * ejc;
                }
                Ev = s;
            }
            Ev = fmaxf(Ev, 1e-30f);
            if (lane < 16) { sP1[e] = Ev; g_P1[z*16 + e] = Ev; }
            else           { sP2[e] = Ev; g_P2[z*16 + e] = Ev; }
        }
        __syncthreads();
        {
            float tot = 0.f;
            #pragma unroll
            for (int a = 0; a < 4; a++) {
                float m1 = sP1[a*4+0]*e10 + sP1[a*4+1]*e11 + sP1[a*4+2]*e12 + sP1[a*4+3]*e13;
                float m2 = sP2[a*4+0]*e20 + sP2[a*4+1]*e21 + sP2[a*4+2]*e22 + sP2[a*4+3]*e23;
                tot += m1 * m2 * sstat[a];
            }
            float val = __logf(tot);
            #pragma unroll
            for (int off = 16; off; off >>= 1)
                val += __shfl_down_sync(0xffffffffu, val, off);
            if (lane == 0) s_red[warp] = val;
        }
        __syncthreads();
        if (tid == 0) {
            float s = 0.f;
            #pragma unroll
            for (int w = 0; w < 8; w++) s += s_red[w];
            g_llnew[z] = s;
        }
    }
}

// ---------------- ksel: per-particle selection. grid = K, block = 32 ----------------
__global__ void __launch_bounds__(32) ksel(
        const int* __restrict__ indexes, const int* __restrict__ lc,
        const float* __restrict__ b1r, const float* __restrict__ b2r,
        const int* __restrict__ idx1a, const int* __restrict__ idx2a,
        const float* __restrict__ br1, const float* __restrict__ br2,
        const float* __restrict__ log_pi, const float* __restrict__ logvp,
        const float* __restrict__ gumbel, const float* __restrict__ logdf,
        float* __restrict__ out) {
    int k = blockIdx.x;
    int lane = threadIdx.x;
    int gk = indexes[k];

    float ck = g_ckept[k*T_ + lane];
    int l = lc[gk*T_ + lane];
    float fl = f_logdf(logdf, l);
    float cc = (l > 1) ? 1.f : 0.f;
    float sb = b1r[gk*R_ + lane] + b2r[gk*R_ + lane];
    #pragma unroll
    for (int off = 16; off; off >>= 1) {
        ck += __shfl_down_sync(0xffffffffu, ck, off);
        fl += __shfl_down_sync(0xffffffffu, fl, off);
        cc += __shfl_down_sync(0xffffffffu, cc, off);
        sb += __shfl_down_sync(0xffffffffu, sb, off);
    }
    float s_ct   = __shfl_sync(0xffffffffu, ck, 0);
    float s_flcT = __shfl_sync(0xffffffffu, fl, 0);
    float s_cT   = __shfl_sync(0xffffffffu, cc, 0);
    float s_sb   = __shfl_sync(0xffffffffu, sb, 0);

    float lw = -1e30f, lpn = 0.f, loglik = 0.f, gum = -1e30f;
    if (lane < J_) {
        int zc = k*J_ + lane;
        int c1 = idx1a[zc], c2 = idx2a[zc];
        loglik = s_ct - g_ckept[k*T_ + c1] - g_ckept[k*T_ + c2] + g_llnew[zc];
        float lbp = 2.f * (float)RP1 * LOG10F - 10.f * (s_sb + br1[zc] + br2[zc]);
        int l1 = lc[gk*T_ + c1], l2 = lc[gk*T_ + c2];
        float flcnew = s_flcT - f_logdf(logdf, l1) - f_logdf(logdf, l2)
                     + f_logdf(logdf, l1 + l2);
        float cnt = s_cT - (float)(l1 > 1) - (float)(l2 > 1) + 1.f;
        lpn = loglik + lbp - flcnew;
        lw = lpn - log_pi[gk] + __logf(cnt) - logvp[zc];
        gum = lw + gumbel[zc];
    }
    float m = lw;
    m = fmaxf(m, __shfl_xor_sync(0xffffffffu, m, 1));
    m = fmaxf(m, __shfl_xor_sync(0xffffffffu, m, 2));
    float ex = (lane < J_) ? __expf(lw - m) : 0.f;
    float se = ex + __shfl_xor_sync(0xffffffffu, ex, 1);
    se += __shfl_xor_sync(0xffffffffu, se, 2);

    float g0 = __shfl_sync(0xffffffffu, gum, 0);
    float g1 = __shfl_sync(0xffffffffu, gum, 1);
    float g2 = __shfl_sync(0xffffffffu, gum, 2);
    float g3 = __shfl_sync(0xffffffffu, gum, 3);
    int best = 0; float bv = g0;
    if (g1 > bv) { bv = g1; best = 1; }
    if (g2 > bv) { bv = g2; best = 2; }
    if (g3 > bv) { bv = g3; best = 3; }
    float lpn_b  = __shfl_sync(0xffffffffu, lpn, best);
    float llik_b = __shfl_sync(0xffffffffu, loglik, best);

    if (lane == 0) {
        int zs = k*J_ + best;
        g_selinfo[k] = make_int4(gk, idx1a[zs], idx2a[zs], zs);
        out[O10 + k] = m + __logf(se) - LOG4F;
        out[O9 + k]  = lpn_b;
        out[O11 + k] = llik_b;
    }
}

// ---------------- Kernel 2: outputs. grid (9, K), block 256 ----------------
__global__ void __launch_bounds__(256, 8) k2(
        const int* __restrict__ lc, const int* __restrict__ hashes,
        const float* __restrict__ embt, const float* __restrict__ lf,
        const float* __restrict__ embJ,
        const float* __restrict__ br1, const float* __restrict__ br2,
        const int* __restrict__ m1r, const int* __restrict__ m2r,
        const float* __restrict__ b1r, const float* __restrict__ b2r,
        const float* __restrict__ embr,
        float* __restrict__ out) {
    int i = blockIdx.x;
    int k = blockIdx.y;
    int tid = threadIdx.x;
    int4 si = g_selinfo[k];
    int gk = si.x, i1 = si.y, i2 = si.z, zs = si.w;
    int a = min(i1, i2), b = max(i1, i2);

    if (i < 7) {
        int nbase = 4*i;
        int tt[4];
        #pragma unroll
        for (int r = 0; r < 4; r++) {
            int t = nbase + r;
            if (t >= a) t++;
            if (t >= b) t++;
            tt[r] = t;
        }
        {
            float4 v0 = ((const float4*)(lf + (size_t)(gk*T_ + tt[0])*S_*A_))[tid];
            float4 v1 = ((const float4*)(lf + (size_t)(gk*T_ + tt[1])*S_*A_))[tid];
            __stcs((float4*)(out + O8 + (size_t)(k*TM1 + nbase + 0)*S_*A_) + tid, v0);
            __stcs((float4*)(out + O8 + (size_t)(k*TM1 + nbase + 1)*S_*A_) + tid, v1);
        }
        {
            float4 v2 = ((const float4*)(lf + (size_t)(gk*T_ + tt[2])*S_*A_))[tid];
            float4 v3 = ((const float4*)(lf + (size_t)(gk*T_ + tt[3])*S_*A_))[tid];
            __stcs((float4*)(out + O8 + (size_t)(k*TM1 + nbase + 2)*S_*A_) + tid, v2);
            __stcs((float4*)(out + O8 + (size_t)(k*TM1 + nbase + 3)*S_*A_) + tid, v3);
        }
        {
            int r = tid >> 6, d = tid & 63;
            out[O7 + (size_t)(k*TM1 + nbase + r)*D_ + d] =
                embt[(size_t)(gk*T_ + tt[r])*D_ + d];
        }
        if (tid < 4) {
            out[O5 + k*TM1 + nbase + tid] = (float)lc[gk*T_ + tt[tid]];
            out[O6 + k*TM1 + nbase + tid] = (float)hashes[gk*T_ + tt[tid]];
        }
    } else if (i == 7) {
        __shared__ float sP1[16], sP2[16];
        if (tid < 16) sP1[tid] = g_P1[zs*16 + tid];
        else if (tid < 32) sP2[tid-16] = g_P2[zs*16 + tid - 16];
        int t0 = 28; if (t0 >= a) t0++; if (t0 >= b) t0++;
        int t1 = 29; if (t1 >= a) t1++; if (t1 >= b) t1++;
        {
            float4 v0 = ((const float4*)(lf + (size_t)(gk*T_ + t0)*S_*A_))[tid];
            float4 v1 = ((const float4*)(lf + (size_t)(gk*T_ + t1)*S_*A_))[tid];
            __stcs((float4*)(out + O8 + (size_t)(k*TM1 + 28)*S_*A_) + tid, v0);
            __stcs((float4*)(out + O8 + (size_t)(k*TM1 + 29)*S_*A_) + tid, v1);
        }
        float4 w1 = ((const float4*)(lf + (size_t)(gk*T_ + i1)*S_*A_))[tid];
        float4 w2 = ((const float4*)(lf + (size_t)(gk*T_ + i2)*S_*A_))[tid];
        __syncthreads();
        {
            float e10=__expf(w1.x), e11=__expf(w1.y), e12=__expf(w1.z), e13=__expf(w1.w);
            float e20=__expf(w2.x), e21=__expf(w2.y), e22=__expf(w2.z), e23=__expf(w2.w);
            float4 res;
            float* rp = (float*)&res;
            #pragma unroll
            for (int aa = 0; aa < 4; aa++) {
                float m1 = sP1[aa*4+0]*e10 + sP1[aa*4+1]*e11 + sP1[aa*4+2]*e12 + sP1[aa*4+3]*e13;
                float m2 = sP2[aa*4+0]*e20 + sP2[aa*4+1]*e21 + sP2[aa*4+2]*e22 + sP2[aa*4+3]*e23;
                rp[aa] = __logf(m1) + __logf(m2);
            }
            __stcs((float4*)(out + O8 + (size_t)(k*TM1 + 30)*S_*A_) + tid, res);
        }
        if (tid < 192) {
            int r = tid >> 6, d = tid & 63;
            float val;
            if (r < 2) {
                int t = (r == 0) ? t0 : t1;
                val = embt[(size_t)(gk*T_ + t)*D_ + d];
            } else {
                val = embJ[(size_t)zs*D_ + d];
            }
            out[O7 + (size_t)(k*TM1 + 28 + r)*D_ + d] = val;
        }
        if (tid < 2) {
            int t = (tid == 0) ? t0 : t1;
            out[O5 + k*TM1 + 28 + tid] = (float)lc[gk*T_ + t];
            out[O6 + k*TM1 + 28 + tid] = (float)hashes[gk*T_ + t];
        } else if (tid == 2) {
            int l1 = lc[gk*T_ + i1], l2 = lc[gk*T_ + i2];
            out[O5 + k*TM1 + 30] = (float)(l1 + l2);
            int h1 = hashes[gk*T_ + i1], h2 = hashes[gk*T_ + i2];
            int mn = min(h1, h2), mx = max(h1, h2);
            unsigned int hh = ((unsigned int)mn * 1000003u + (unsigned int)mx) * 40503u + 2531011u;
            out[O6 + k*TM1 + 30] = (float)(int)hh;
        }
    } else {
        if (tid < RP1) {
            int r = tid;
            float v1, v2, vb1, vb2;
            if (r < R_) {
                v1 = (float)m1r[gk*R_ + r];
                v2 = (float)m2r[gk*R_ + r];
                vb1 = b1r[gk*R_ + r];
                vb2 = b2r[gk*R_ + r];
            } else {
                v1 = (float)i1; v2 = (float)i2;
                vb1 = br1[zs];  vb2 = br2[zs];
            }
            out[O0 + k*RP1 + r] = v1;
            out[O1 + k*RP1 + r] = v2;
            out[O2 + k*RP1 + r] = vb1;
            out[O3 + k*RP1 + r] = vb2;
        }
        const float4* s4 = (const float4*)(embr + (size_t)gk*R_*D_);
        float4* d4 = (float4*)(out + O4 + (size_t)k*RP1*D_);
        d4[tid] = s4[tid];
        d4[tid + 256] = s4[tid + 256];
        if (tid < 16) {
            const float4* j4 = (const float4*)(embJ + (size_t)zs*D_);
            d4[512 + tid] = j4[tid];
        }
    }
}

// ---------------- launch ----------------
extern "C" void kernel_launch(void* const* d_in, const int* in_sizes, int n_in,
                              void* d_out, int out_size) {
    const int*   indexes = (const int*)  d_in[0];
    const int*   m1r     = (const int*)  d_in[1];
    const int*   m2r     = (const int*)  d_in[2];
    const float* b1r     = (const float*)d_in[3];
    const float* b2r     = (const float*)d_in[4];
    const float* embr    = (const float*)d_in[5];
    const int*   lc      = (const int*)  d_in[6];
    const int*   hashes  = (const int*)  d_in[7];
    const float* embt    = (const float*)d_in[8];
    const float* lf      = (const float*)d_in[9];
    const float* log_pi  = (const float*)d_in[10];
    const int*   idx1a   = (const int*)  d_in[11];
    const int*   idx2a   = (const int*)  d_in[12];
    const float* br1     = (const float*)d_in[13];
    const float* br2     = (const float*)d_in[14];
    const float* embJ    = (const float*)d_in[15];
    const float* logvp   = (const float*)d_in[16];
    const float* gumbel  = (const float*)d_in[17];
    const float* Wq      = (const float*)d_in[18];
    const float* Wstat   = (const float*)d_in[19];
    const float* logdf   = (const float*)d_in[20];
    float* out = (float*)d_out;

    k1<<<2*K_ + Z_, 256>>>(indexes, lc, embt, lf, Wstat,
                           idx1a, idx2a, br1, br2, embJ, Wq);
    ksel<<<K_, 32>>>(indexes, lc, b1r, b2r, idx1a, idx2a, br1, br2,
                     log_pi, logvp, gumbel, logdf, out);
    k2<<<dim3(9, K_), 256>>>(lc, hashes, embt, lf, embJ, br1, br2,
                             m1r, m2r, b1r, b2r, embr, out);
}

// round 12
// speedup vs baseline: 1.0118x; 1.0118x over previous
#include <cuda_runtime.h>
#include <cuda_bf16.h>
#include <math.h>

// Problem constants
#define K_ 128
#define J_ 4
#define N_ 64
#define R_ 32
#define T_ 32
#define S_ 256
#define A_ 4
#define D_ 64
#define Z_ (K_*J_)   // 512
#define TM1 (T_-1)   // 31
#define RP1 (R_+1)   // 33

// Output segment offsets (floats)
#define O0 0u
#define O1 4224u
#define O2 8448u
#define O3 12672u
#define O4 16896u
#define O5 287232u
#define O6 291200u
#define O7 295168u
#define O8 549120u
#define O9 4612352u
#define O10 4612480u
#define O11 4612608u

#define LOG10F 2.302585092994045684f
#define LOG4F  1.3862943611198906f

// ---------------- scratch ----------------
__device__ float g_ckept[K_*T_];
__device__ float g_llnew[Z_];
__device__ float g_P1[Z_*16];
__device__ float g_P2[Z_*16];
__device__ int   g_cnt[K_];       // producer arrivals (zero-init; selector resets)
__device__ int4  g_selinfo[K_];   // {gk, i1, i2, zs}

__device__ __forceinline__ float f_logdf(const float* logdf, int l) {
    int di = 2*l - 3;
    di = max(0, min(2*N_ - 1, di));
    return logdf[di];
}

// ---------------- Kernel 1 ----------------
// blocks [0,2K): kA halves (2 rows/warp).  [2K,2K+Z): kB candidates.
// [2K+Z, 2K+Z+K): per-particle selectors (spin until 6 producers arrive).
__global__ void __launch_bounds__(256, 6) k1(
        const int* __restrict__ indexes,
        const int* __restrict__ lc, const float* __restrict__ embt,
        const float* __restrict__ lf, const float* __restrict__ Wstat,
        const int* __restrict__ idx1a, const int* __restrict__ idx2a,
        const float* __restrict__ br1, const float* __restrict__ br2,
        const float* __restrict__ embJ, const float* __restrict__ Wq,
        const float* __restrict__ b1r, const float* __restrict__ b2r,
        const float* __restrict__ log_pi, const float* __restrict__ logvp,
        const float* __restrict__ gumbel, const float* __restrict__ logdf,
        float* __restrict__ out) {
    int tid = threadIdx.x;
    int warp = tid >> 5, lane = tid & 31;

    if (blockIdx.x < 2*K_) {
        // ----- kA half: rows h*16 + warp and h*16 + warp + 8 -----
        int k = blockIdx.x >> 1, h = blockIdx.x & 1;
        int gk = indexes[k];
        int tA = h*16 + warp;
        int tB = tA + 8;

        const float2* eA2 = (const float2*)(embt + (size_t)(gk*T_ + tA)*D_);
        const float2* eB2 = (const float2*)(embt + (size_t)(gk*T_ + tB)*D_);
        float2 ea = eA2[lane];
        float2 eb = eB2[lane];
        const float4* w4 = (const float4*)Wstat;
        float4 wa = w4[2*lane], wb = w4[2*lane + 1];
        float a0 = ea.x*wa.x + ea.y*wb.x;
        float a1 = ea.x*wa.y + ea.y*wb.y;
        float a2 = ea.x*wa.z + ea.y*wb.z;
        float a3 = ea.x*wa.w + ea.y*wb.w;
        float b0 = eb.x*wa.x + eb.y*wb.x;
        float b1 = eb.x*wa.y + eb.y*wb.y;
        float b2 = eb.x*wa.z + eb.y*wb.z;
        float b3 = eb.x*wa.w + eb.y*wb.w;
        #pragma unroll
        for (int off = 16; off; off >>= 1) {
            a0 += __shfl_xor_sync(0xffffffffu, a0, off);
            a1 += __shfl_xor_sync(0xffffffffu, a1, off);
            a2 += __shfl_xor_sync(0xffffffffu, a2, off);
            a3 += __shfl_xor_sync(0xffffffffu, a3, off);
            b0 += __shfl_xor_sync(0xffffffffu, b0, off);
            b1 += __shfl_xor_sync(0xffffffffu, b1, off);
            b2 += __shfl_xor_sync(0xffffffffu, b2, off);
            b3 += __shfl_xor_sync(0xffffffffu, b3, off);
        }
        float mA = fmaxf(fmaxf(a0, a1), fmaxf(a2, a3));
        float pA0 = __expf(a0 - mA), pA1 = __expf(a1 - mA);
        float pA2 = __expf(a2 - mA), pA3 = __expf(a3 - mA);
        float invA = 1.f / (pA0 + pA1 + pA2 + pA3);
        pA0 *= invA; pA1 *= invA; pA2 *= invA; pA3 *= invA;
        float mB = fmaxf(fmaxf(b0, b1), fmaxf(b2, b3));
        float pB0 = __expf(b0 - mB), pB1 = __expf(b1 - mB);
        float pB2 = __expf(b2 - mB), pB3 = __expf(b3 - mB);
        float invB = 1.f / (pB0 + pB1 + pB2 + pB3);
        pB0 *= invB; pB1 *= invB; pB2 *= invB; pB3 *= invB;

        const float4* rowA = (const float4*)(lf + (size_t)(gk*T_ + tA)*S_*A_);
        const float4* rowB = (const float4*)(lf + (size_t)(gk*T_ + tB)*S_*A_);
        float prodA0 = 1.f, prodA1v = 1.f, prodB0 = 1.f, prodB1v = 1.f;
        #pragma unroll
        for (int g = 0; g < 4; g++) {
            float4 vA0 = rowA[lane + 32*(2*g)];
            float4 vA1 = rowA[lane + 32*(2*g + 1)];
            float4 vB0 = rowB[lane + 32*(2*g)];
            float4 vB1 = rowB[lane + 32*(2*g + 1)];
            float dA0 = pA0*__expf(vA0.x) + pA1*__expf(vA0.y)
                      + pA2*__expf(vA0.z) + pA3*__expf(vA0.w);
            float dA1 = pA0*__expf(vA1.x) + pA1*__expf(vA1.y)
                      + pA2*__expf(vA1.z) + pA3*__expf(vA1.w);
            float dB0 = pB0*__expf(vB0.x) + pB1*__expf(vB0.y)
                      + pB2*__expf(vB0.z) + pB3*__expf(vB0.w);
            float dB1 = pB0*__expf(vB1.x) + pB1*__expf(vB1.y)
                      + pB2*__expf(vB1.z) + pB3*__expf(vB1.w);
            prodA0 *= dA0; prodA1v *= dA1;
            prodB0 *= dB0; prodB1v *= dB1;
        }
        float accA = __logf(prodA0 * prodA1v);
        float accB = __logf(prodB0 * prodB1v);
        #pragma unroll
        for (int off = 16; off; off >>= 1) {
            accA += __shfl_xor_sync(0xffffffffu, accA, off);
            accB += __shfl_xor_sync(0xffffffffu, accB, off);
        }
        if (lane == 0) {
            g_ckept[k*T_ + tA] = accA;
            g_ckept[k*T_ + tB] = accB;
        }
        // producer arrive
        __syncthreads();
        if (tid == 0) { __threadfence(); atomicAdd(&g_cnt[k], 1); }
    } else if (blockIdx.x < 2*K_ + Z_) {
        // ----- kB candidate z -----
        int z = blockIdx.x - 2*K_;
        int k = z / J_;
        int gk = indexes[k];
        __shared__ float slog[20];
        __shared__ float sP1[16], sP2[16], sstat[4];
        __shared__ float s_red[8];

        int i1 = idx1a[z], i2 = idx2a[z];
        float bb1 = br1[z], bb2 = br2[z];

        const float4* r1 = (const float4*)(lf + (size_t)(gk*T_ + i1)*S_*A_);
        const float4* r2 = (const float4*)(lf + (size_t)(gk*T_ + i2)*S_*A_);
        float4 w1 = r1[tid], w2 = r2[tid];
        float e10=__expf(w1.x), e11=__expf(w1.y), e12=__expf(w1.z), e13=__expf(w1.w);
        float e20=__expf(w2.x), e21=__expf(w2.y), e22=__expf(w2.z), e23=__expf(w2.w);

        if (warp < 5) {
            const float2* emb2 = (const float2*)(embJ + (size_t)z*D_);
            float2 e = emb2[lane];
            float l0, l1, l2, l3;
            if (warp < 4) {
                int col = 4*warp;
                const float* Wq0 = Wq + (2*lane)*16 + col;
                const float* Wq1 = Wq + (2*lane + 1)*16 + col;
                l0 = e.x*Wq0[0] + e.y*Wq1[0];
                l1 = e.x*Wq0[1] + e.y*Wq1[1];
                l2 = e.x*Wq0[2] + e.y*Wq1[2];
                l3 = e.x*Wq0[3] + e.y*Wq1[3];
            } else {
                const float4* ws4 = (const float4*)Wstat;
                float4 wsa = ws4[2*lane], wsb = ws4[2*lane + 1];
                l0 = e.x*wsa.x + e.y*wsb.x;
                l1 = e.x*wsa.y + e.y*wsb.y;
                l2 = e.x*wsa.z + e.y*wsb.z;
                l3 = e.x*wsa.w + e.y*wsb.w;
            }
            #pragma unroll
            for (int off = 16; off; off >>= 1) {
                l0 += __shfl_xor_sync(0xffffffffu, l0, off);
                l1 += __shfl_xor_sync(0xffffffffu, l1, off);
                l2 += __shfl_xor_sync(0xffffffffu, l2, off);
                l3 += __shfl_xor_sync(0xffffffffu, l3, off);
            }
            if (lane == 0) {
                slog[4*warp + 0] = l0;
                slog[4*warp + 1] = l1;
                slog[4*warp + 2] = l2;
                slog[4*warp + 3] = l3;
            }
        }
        __syncthreads();

        if (warp == 0) {
            float logit = (lane < 20) ? slog[lane] : 0.f;
            {
                float mm = fmaxf(logit, __shfl_xor_sync(0xffffffffu, logit, 1));
                mm = fmaxf(mm, __shfl_xor_sync(0xffffffffu, mm, 2));
                float ex = __expf(logit - mm);
                float ttl = ex + __shfl_xor_sync(0xffffffffu, ex, 1);
                ttl += __shfl_xor_sync(0xffffffffu, ttl, 2);
                if (lane >= 16 && lane < 20) sstat[lane - 16] = ex / ttl;
            }
            int e = lane & 15, r = e >> 2, c = e & 3;
            float qoff = 0.f;
            if (lane < 16) {
                float x = logit;
                float sp = fmaxf(x, 0.f) + log1pf(__expf(-fabsf(x)));
                qoff = (r == c) ? 0.f : sp;
            }
            float s1 = qoff + __shfl_xor_sync(0xffffffffu, qoff, 1);
            float rs = s1 + __shfl_xor_sync(0xffffffffu, s1, 2);
            float Qown = (r == c) ? -rs : qoff;
            float Qe = __shfl_sync(0xffffffffu, Qown, lane & 15);

            int base = lane & 16;
            float bsc = ((lane < 16) ? bb1 : bb2) * 0.125f;
            float Av = Qe * bsc;
            float Ev = Av + ((r == c) ? 1.f : 0.f);
            float Tm = Av;
            #pragma unroll
            for (int n = 2; n <= 7; n++) {
                float s = 0.f;
                #pragma unroll
                for (int j = 0; j < 4; j++) {
                    float trj = __shfl_sync(0xffffffffu, Tm, base + (r<<2) + j);
                    float ajc = __shfl_sync(0xffffffffu, Av, base + (j<<2) + c);
                    s += trj * ajc;
                }
                Tm = s * (1.f / (float)n);
                Ev += Tm;
            }
            #pragma unroll
            for (int qq = 0; qq < 3; qq++) {
                float s = 0.f;
                #pragma unroll
                for (int j = 0; j < 4; j++) {
                    float erj = __shfl_sync(0xffffffffu, Ev, base + (r<<2) + j);
                    float ejc = __shfl_sync(0xffffffffu, Ev, base + (j<<2) + c);
                    s += erj * ejc;
                }
                Ev = s;
            }
            Ev = fmaxf(Ev, 1e-30f);
            if (lane < 16) { sP1[e] = Ev; g_P1[z*16 + e] = Ev; }
            else           { sP2[e] = Ev; g_P2[z*16 + e] = Ev; }
        }
        __syncthreads();
        {
            float tot = 0.f;
            #pragma unroll
            for (int a = 0; a < 4; a++) {
                float m1 = sP1[a*4+0]*e10 + sP1[a*4+1]*e11 + sP1[a*4+2]*e12 + sP1[a*4+3]*e13;
                float m2 = sP2[a*4+0]*e20 + sP2[a*4+1]*e21 + sP2[a*4+2]*e22 + sP2[a*4+3]*e23;
                tot += m1 * m2 * sstat[a];
            }
            float val = __logf(tot);
            #pragma unroll
            for (int off = 16; off; off >>= 1)
                val += __shfl_down_sync(0xffffffffu, val, off);
            if (lane == 0) s_red[warp] = val;
        }
        __syncthreads();
        if (tid == 0) {
            float s = 0.f;
            #pragma unroll
            for (int w = 0; w < 8; w++) s += s_red[w];
            g_llnew[z] = s;
            __threadfence();
            atomicAdd(&g_cnt[k], 1);
        }
    } else {
        // ----- selector block for particle k: spin until 6 producers done -----
        int k = blockIdx.x - (2*K_ + Z_);
        if (tid == 0) {
            while (*((volatile int*)&g_cnt[k]) < 6) __nanosleep(64);
            __threadfence();   // acquire
        }
        __syncthreads();
        if (warp == 0) {
            int gk = indexes[k];
            float ck = g_ckept[k*T_ + lane];
            int l = lc[gk*T_ + lane];
            float fl = f_logdf(logdf, l);
            float cc = (l > 1) ? 1.f : 0.f;
            float sb = b1r[gk*R_ + lane] + b2r[gk*R_ + lane];
            #pragma unroll
            for (int off = 16; off; off >>= 1) {
                ck += __shfl_down_sync(0xffffffffu, ck, off);
                fl += __shfl_down_sync(0xffffffffu, fl, off);
                cc += __shfl_down_sync(0xffffffffu, cc, off);
                sb += __shfl_down_sync(0xffffffffu, sb, off);
            }
            float s_ct   = __shfl_sync(0xffffffffu, ck, 0);
            float s_flcT = __shfl_sync(0xffffffffu, fl, 0);
            float s_cT   = __shfl_sync(0xffffffffu, cc, 0);
            float s_sb   = __shfl_sync(0xffffffffu, sb, 0);

            float lw = -1e30f, lpn = 0.f, loglik = 0.f, gum = -1e30f;
            if (lane < J_) {
                int zc = k*J_ + lane;
                int c1 = idx1a[zc], c2 = idx2a[zc];
                loglik = s_ct - g_ckept[k*T_ + c1] - g_ckept[k*T_ + c2] + g_llnew[zc];
                float lbp = 2.f * (float)RP1 * LOG10F - 10.f * (s_sb + br1[zc] + br2[zc]);
                int l1 = lc[gk*T_ + c1], l2 = lc[gk*T_ + c2];
                float flcnew = s_flcT - f_logdf(logdf, l1) - f_logdf(logdf, l2)
                             + f_logdf(logdf, l1 + l2);
                float cnt = s_cT - (float)(l1 > 1) - (float)(l2 > 1) + 1.f;
                lpn = loglik + lbp - flcnew;
                lw = lpn - log_pi[gk] + __logf(cnt) - logvp[zc];
                gum = lw + gumbel[zc];
            }
            float m = lw;
            m = fmaxf(m, __shfl_xor_sync(0xffffffffu, m, 1));
            m = fmaxf(m, __shfl_xor_sync(0xffffffffu, m, 2));
            float ex = (lane < J_) ? __expf(lw - m) : 0.f;
            float se = ex + __shfl_xor_sync(0xffffffffu, ex, 1);
            se += __shfl_xor_sync(0xffffffffu, se, 2);

            float g0 = __shfl_sync(0xffffffffu, gum, 0);
            float g1 = __shfl_sync(0xffffffffu, gum, 1);
            float g2 = __shfl_sync(0xffffffffu, gum, 2);
            float g3 = __shfl_sync(0xffffffffu, gum, 3);
            int best = 0; float bv = g0;
            if (g1 > bv) { bv = g1; best = 1; }
            if (g2 > bv) { bv = g2; best = 2; }
            if (g3 > bv) { bv = g3; best = 3; }
            float lpn_b  = __shfl_sync(0xffffffffu, lpn, best);
            float llik_b = __shfl_sync(0xffffffffu, loglik, best);

            if (lane == 0) {
                int zs = k*J_ + best;
                g_selinfo[k] = make_int4(gk, idx1a[zs], idx2a[zs], zs);
                out[O10 + k] = m + __logf(se) - LOG4F;
                out[O9 + k]  = lpn_b;
                out[O11 + k] = llik_b;
                g_cnt[k] = 0;     // reset for next graph replay
            }
        }
    }
}

// ---------------- Kernel 2: outputs. grid (9, K), block 256 ----------------
__global__ void __launch_bounds__(256, 8) k2(
        const int* __restrict__ lc, const int* __restrict__ hashes,
        const float* __restrict__ embt, const float* __restrict__ lf,
        const float* __restrict__ embJ,
        const float* __restrict__ br1, const float* __restrict__ br2,
        const int* __restrict__ m1r, const int* __restrict__ m2r,
        const float* __restrict__ b1r, const float* __restrict__ b2r,
        const float* __restrict__ embr,
        float* __restrict__ out) {
    int i = blockIdx.x;
    int k = blockIdx.y;
    int tid = threadIdx.x;
    int4 si = g_selinfo[k];
    int gk = si.x, i1 = si.y, i2 = si.z, zs = si.w;
    int a = min(i1, i2), b = max(i1, i2);

    if (i < 7) {
        int nbase = 4*i;
        int tt[4];
        #pragma unroll
        for (int r = 0; r < 4; r++) {
            int t = nbase + r;
            if (t >= a) t++;
            if (t >= b) t++;
            tt[r] = t;
        }
        {
            float4 v0 = ((const float4*)(lf + (size_t)(gk*T_ + tt[0])*S_*A_))[tid];
            float4 v1 = ((const float4*)(lf + (size_t)(gk*T_ + tt[1])*S_*A_))[tid];
            __stcs((float4*)(out + O8 + (size_t)(k*TM1 + nbase + 0)*S_*A_) + tid, v0);
            __stcs((float4*)(out + O8 + (size_t)(k*TM1 + nbase + 1)*S_*A_) + tid, v1);
        }
        {
            float4 v2 = ((const float4*)(lf + (size_t)(gk*T_ + tt[2])*S_*A_))[tid];
            float4 v3 = ((const float4*)(lf + (size_t)(gk*T_ + tt[3])*S_*A_))[tid];
            __stcs((float4*)(out + O8 + (size_t)(k*TM1 + nbase + 2)*S_*A_) + tid, v2);
            __stcs((float4*)(out + O8 + (size_t)(k*TM1 + nbase + 3)*S_*A_) + tid, v3);
        }
        {
            int r = tid >> 6, d = tid & 63;
            out[O7 + (size_t)(k*TM1 + nbase + r)*D_ + d] =
                embt[(size_t)(gk*T_ + tt[r])*D_ + d];
        }
        if (tid < 4) {
            out[O5 + k*TM1 + nbase + tid] = (float)lc[gk*T_ + tt[tid]];
            out[O6 + k*TM1 + nbase + tid] = (float)hashes[gk*T_ + tt[tid]];
        }
    } else if (i == 7) {
        __shared__ float sP1[16], sP2[16];
        if (tid < 16) sP1[tid] = g_P1[zs*16 + tid];
        else if (tid < 32) sP2[tid-16] = g_P2[zs*16 + tid - 16];
        int t0 = 28; if (t0 >= a) t0++; if (t0 >= b) t0++;
        int t1 = 29; if (t1 >= a) t1++; if (t1 >= b) t1++;
        {
            float4 v0 = ((const float4*)(lf + (size_t)(gk*T_ + t0)*S_*A_))[tid];
            float4 v1 = ((const float4*)(lf + (size_t)(gk*T_ + t1)*S_*A_))[tid];
            __stcs((float4*)(out + O8 + (size_t)(k*TM1 + 28)*S_*A_) + tid, v0);
            __stcs((float4*)(out + O8 + (size_t)(k*TM1 + 29)*S_*A_) + tid, v1);
        }
        float4 w1 = ((const float4*)(lf + (size_t)(gk*T_ + i1)*S_*A_))[tid];
        float4 w2 = ((const float4*)(lf + (size_t)(gk*T_ + i2)*S_*A_))[tid];
        __syncthreads();
        {
            float e10=__expf(w1.x), e11=__expf(w1.y), e12=__expf(w1.z), e13=__expf(w1.w);
            float e20=__expf(w2.x), e21=__expf(w2.y), e22=__expf(w2.z), e23=__expf(w2.w);
            float4 res;
            float* rp = (float*)&res;
            #pragma unroll
            for (int aa = 0; aa < 4; aa++) {
                float m1 = sP1[aa*4+0]*e10 + sP1[aa*4+1]*e11 + sP1[aa*4+2]*e12 + sP1[aa*4+3]*e13;
                float m2 = sP2[aa*4+0]*e20 + sP2[aa*4+1]*e21 + sP2[aa*4+2]*e22 + sP2[aa*4+3]*e23;
                rp[aa] = __logf(m1) + __logf(m2);
            }
            __stcs((float4*)(out + O8 + (size_t)(k*TM1 + 30)*S_*A_) + tid, res);
        }
        if (tid < 192) {
            int r = tid >> 6, d = tid & 63;
            float val;
            if (r < 2) {
                int t = (r == 0) ? t0 : t1;
                val = embt[(size_t)(gk*T_ + t)*D_ + d];
            } else {
                val = embJ[(size_t)zs*D_ + d];
            }
            out[O7 + (size_t)(k*TM1 + 28 + r)*D_ + d] = val;
        }
        if (tid < 2) {
            int t = (tid == 0) ? t0 : t1;
            out[O5 + k*TM1 + 28 + tid] = (float)lc[gk*T_ + t];
            out[O6 + k*TM1 + 28 + tid] = (float)hashes[gk*T_ + t];
        } else if (tid == 2) {
            int l1 = lc[gk*T_ + i1], l2 = lc[gk*T_ + i2];
            out[O5 + k*TM1 + 30] = (float)(l1 + l2);
            int h1 = hashes[gk*T_ + i1], h2 = hashes[gk*T_ + i2];
            int mn = min(h1, h2), mx = max(h1, h2);
            unsigned int hh = ((unsigned int)mn * 1000003u + (unsigned int)mx) * 40503u + 2531011u;
            out[O6 + k*TM1 + 30] = (float)(int)hh;
        }
    } else {
        if (tid < RP1) {
            int r = tid;
            float v1, v2, vb1, vb2;
            if (r < R_) {
                v1 = (float)m1r[gk*R_ + r];
                v2 = (float)m2r[gk*R_ + r];
                vb1 = b1r[gk*R_ + r];
                vb2 = b2r[gk*R_ + r];
            } else {
                v1 = (float)i1; v2 = (float)i2;
                vb1 = br1[zs];  vb2 = br2[zs];
            }
            out[O0 + k*RP1 + r] = v1;
            out[O1 + k*RP1 + r] = v2;
            out[O2 + k*RP1 + r] = vb1;
            out[O3 + k*RP1 + r] = vb2;
        }
        const float4* s4 = (const float4*)(embr + (size_t)gk*R_*D_);
        float4* d4 = (float4*)(out + O4 + (size_t)k*RP1*D_);
        d4[tid] = s4[tid];
        d4[tid + 256] = s4[tid + 256];
        if (tid < 16) {
            const float4* j4 = (const float4*)(embJ + (size_t)zs*D_);
            d4[512 + tid] = j4[tid];
        }
    }
}

// ---------------- launch ----------------
extern "C" void kernel_launch(void* const* d_in, const int* in_sizes, int n_in,
                              void* d_out, int out_size) {
    const int*   indexes = (const int*)  d_in[0];
    const int*   m1r     = (const int*)  d_in[1];
    const int*   m2r     = (const int*)  d_in[2];
    const float* b1r     = (const float*)d_in[3];
    const float* b2r     = (const float*)d_in[4];
    const float* embr    = (const float*)d_in[5];
    const int*   lc      = (const int*)  d_in[6];
    const int*   hashes  = (const int*)  d_in[7];
    const float* embt    = (const float*)d_in[8];
    const float* lf      = (const float*)d_in[9];
    const float* log_pi  = (const float*)d_in[10];
    const int*   idx1a   = (const int*)  d_in[11];
    const int*   idx2a   = (const int*)  d_in[12];
    const float* br1     = (const float*)d_in[13];
    const float* br2     = (const float*)d_in[14];
    const float* embJ    = (const float*)d_in[15];
    const float* logvp   = (const float*)d_in[16];
    const float* gumbel  = (const float*)d_in[17];
    const float* Wq      = (const float*)d_in[18];
    const float* Wstat   = (const float*)d_in[19];
    const float* logdf   = (const float*)d_in[20];
    float* out = (float*)d_out;

    k1<<<2*K_ + Z_ + K_, 256>>>(indexes, lc, embt, lf, Wstat,
                                idx1a, idx2a, br1, br2, embJ, Wq,
                                b1r, b2r, log_pi, logvp, gumbel, logdf, out);
    k2<<<dim3(9, K_), 256>>>(lc, hashes, embt, lf, embJ, br1, br2,
                             m1r, m2r, b1r, b2r, embr, out);
}

// round 13
// speedup vs baseline: 1.0135x; 1.0017x over previous
#include <cuda_runtime.h>
#include <cuda_bf16.h>
#include <math.h>

// Problem constants
#define K_ 128
#define J_ 4
#define N_ 64
#define R_ 32
#define T_ 32
#define S_ 256
#define A_ 4
#define D_ 64
#define Z_ (K_*J_)   // 512
#define TM1 (T_-1)   // 31
#define RP1 (R_+1)   // 33

// Output segment offsets (floats)
#define O0 0u
#define O1 4224u
#define O2 8448u
#define O3 12672u
#define O4 16896u
#define O5 287232u
#define O6 291200u
#define O7 295168u
#define O8 549120u
#define O9 4612352u
#define O10 4612480u
#define O11 4612608u

#define LOG10F 2.302585092994045684f
#define LOG4F  1.3862943611198906f

// ---------------- scratch ----------------
__device__ float g_ckept[K_*T_];
__device__ float g_llnew[Z_];
__device__ float g_P1[Z_*16];
__device__ float g_P2[Z_*16];
__device__ int   g_cnt[K_];       // producer arrivals (zero-init; selector resets)
__device__ int4  g_selinfo[K_];   // {gk, i1, i2, zs}

__device__ __forceinline__ float f_logdf(const float* logdf, int l) {
    int di = 2*l - 3;
    di = max(0, min(2*N_ - 1, di));
    return logdf[di];
}

// ---------------- Kernel 1 ----------------
// blocks [0,2K): kA halves (2 rows/warp).  [2K,2K+Z): kB candidates.
// [2K+Z, 2K+Z+K): per-particle selectors (spin until 6 producers arrive).
__global__ void __launch_bounds__(256, 6) k1(
        const int* __restrict__ indexes,
        const int* __restrict__ lc, const float* __restrict__ embt,
        const float* __restrict__ lf, const float* __restrict__ Wstat,
        const int* __restrict__ idx1a, const int* __restrict__ idx2a,
        const float* __restrict__ br1, const float* __restrict__ br2,
        const float* __restrict__ embJ, const float* __restrict__ Wq,
        const float* __restrict__ b1r, const float* __restrict__ b2r,
        const float* __restrict__ log_pi, const float* __restrict__ logvp,
        const float* __restrict__ gumbel, const float* __restrict__ logdf,
        float* __restrict__ out) {
    int tid = threadIdx.x;
    int warp = tid >> 5, lane = tid & 31;

    if (blockIdx.x < 2*K_) {
        // ----- kA half: rows h*16 + warp and h*16 + warp + 8 -----
        int k = blockIdx.x >> 1, h = blockIdx.x & 1;
        int gk = indexes[k];
        int tA = h*16 + warp;
        int tB = tA + 8;

        const float2* eA2 = (const float2*)(embt + (size_t)(gk*T_ + tA)*D_);
        const float2* eB2 = (const float2*)(embt + (size_t)(gk*T_ + tB)*D_);
        float2 ea = eA2[lane];
        float2 eb = eB2[lane];
        const float4* w4 = (const float4*)Wstat;
        float4 wa = w4[2*lane], wb = w4[2*lane + 1];
        float a0 = ea.x*wa.x + ea.y*wb.x;
        float a1 = ea.x*wa.y + ea.y*wb.y;
        float a2 = ea.x*wa.z + ea.y*wb.z;
        float a3 = ea.x*wa.w + ea.y*wb.w;
        float b0 = eb.x*wa.x + eb.y*wb.x;
        float b1 = eb.x*wa.y + eb.y*wb.y;
        float b2 = eb.x*wa.z + eb.y*wb.z;
        float b3 = eb.x*wa.w + eb.y*wb.w;
        #pragma unroll
        for (int off = 16; off; off >>= 1) {
            a0 += __shfl_xor_sync(0xffffffffu, a0, off);
            a1 += __shfl_xor_sync(0xffffffffu, a1, off);
            a2 += __shfl_xor_sync(0xffffffffu, a2, off);
            a3 += __shfl_xor_sync(0xffffffffu, a3, off);
            b0 += __shfl_xor_sync(0xffffffffu, b0, off);
            b1 += __shfl_xor_sync(0xffffffffu, b1, off);
            b2 += __shfl_xor_sync(0xffffffffu, b2, off);
            b3 += __shfl_xor_sync(0xffffffffu, b3, off);
        }
        float mA = fmaxf(fmaxf(a0, a1), fmaxf(a2, a3));
        float pA0 = __expf(a0 - mA), pA1 = __expf(a1 - mA);
        float pA2 = __expf(a2 - mA), pA3 = __expf(a3 - mA);
        float invA = 1.f / (pA0 + pA1 + pA2 + pA3);
        pA0 *= invA; pA1 *= invA; pA2 *= invA; pA3 *= invA;
        float mB = fmaxf(fmaxf(b0, b1), fmaxf(b2, b3));
        float pB0 = __expf(b0 - mB), pB1 = __expf(b1 - mB);
        float pB2 = __expf(b2 - mB), pB3 = __expf(b3 - mB);
        float invB = 1.f / (pB0 + pB1 + pB2 + pB3);
        pB0 *= invB; pB1 *= invB; pB2 *= invB; pB3 *= invB;

        const float4* rowA = (const float4*)(lf + (size_t)(gk*T_ + tA)*S_*A_);
        const float4* rowB = (const float4*)(lf + (size_t)(gk*T_ + tB)*S_*A_);
        float prodA0 = 1.f, prodA1v = 1.f, prodB0 = 1.f, prodB1v = 1.f;
        #pragma unroll
        for (int g = 0; g < 4; g++) {
            float4 vA0 = rowA[lane + 32*(2*g)];
            float4 vA1 = rowA[lane + 32*(2*g + 1)];
            float4 vB0 = rowB[lane + 32*(2*g)];
            float4 vB1 = rowB[lane + 32*(2*g + 1)];
            float dA0 = pA0*__expf(vA0.x) + pA1*__expf(vA0.y)
                      + pA2*__expf(vA0.z) + pA3*__expf(vA0.w);
            float dA1 = pA0*__expf(vA1.x) + pA1*__expf(vA1.y)
                      + pA2*__expf(vA1.z) + pA3*__expf(vA1.w);
            float dB0 = pB0*__expf(vB0.x) + pB1*__expf(vB0.y)
                      + pB2*__expf(vB0.z) + pB3*__expf(vB0.w);
            float dB1 = pB0*__expf(vB1.x) + pB1*__expf(vB1.y)
                      + pB2*__expf(vB1.z) + pB3*__expf(vB1.w);
            prodA0 *= dA0; prodA1v *= dA1;
            prodB0 *= dB0; prodB1v *= dB1;
        }
        float accA = __logf(prodA0 * prodA1v);
        float accB = __logf(prodB0 * prodB1v);
        #pragma unroll
        for (int off = 16; off; off >>= 1) {
            accA += __shfl_xor_sync(0xffffffffu, accA, off);
            accB += __shfl_xor_sync(0xffffffffu, accB, off);
        }
        if (lane == 0) {
            g_ckept[k*T_ + tA] = accA;
            g_ckept[k*T_ + tB] = accB;
        }
        __syncthreads();
        if (tid == 0) { __threadfence(); atomicAdd(&g_cnt[k], 1); }
    } else if (blockIdx.x < 2*K_ + Z_) {
        // ----- kB candidate z -----
        int z = blockIdx.x - 2*K_;
        int k = z / J_;
        int gk = indexes[k];
        __shared__ float slog[20];
        __shared__ float sP1[16], sP2[16], sstat[4];
        __shared__ float s_red[8];

        int i1 = idx1a[z], i2 = idx2a[z];
        float bb1 = br1[z], bb2 = br2[z];

        const float4* r1 = (const float4*)(lf + (size_t)(gk*T_ + i1)*S_*A_);
        const float4* r2 = (const float4*)(lf + (size_t)(gk*T_ + i2)*S_*A_);
        float4 w1 = r1[tid], w2 = r2[tid];
        float e10=__expf(w1.x), e11=__expf(w1.y), e12=__expf(w1.z), e13=__expf(w1.w);
        float e20=__expf(w2.x), e21=__expf(w2.y), e22=__expf(w2.z), e23=__expf(w2.w);

        if (warp < 5) {
            const float2* emb2 = (const float2*)(embJ + (size_t)z*D_);
            float2 e = emb2[lane];
            float l0, l1, l2, l3;
            if (warp < 4) {
                int col = 4*warp;
                const float* Wq0 = Wq + (2*lane)*16 + col;
                const float* Wq1 = Wq + (2*lane + 1)*16 + col;
                l0 = e.x*Wq0[0] + e.y*Wq1[0];
                l1 = e.x*Wq0[1] + e.y*Wq1[1];
                l2 = e.x*Wq0[2] + e.y*Wq1[2];
                l3 = e.x*Wq0[3] + e.y*Wq1[3];
            } else {
                const float4* ws4 = (const float4*)Wstat;
                float4 wsa = ws4[2*lane], wsb = ws4[2*lane + 1];
                l0 = e.x*wsa.x + e.y*wsb.x;
                l1 = e.x*wsa.y + e.y*wsb.y;
                l2 = e.x*wsa.z + e.y*wsb.z;
                l3 = e.x*wsa.w + e.y*wsb.w;
            }
            #pragma unroll
            for (int off = 16; off; off >>= 1) {
                l0 += __shfl_xor_sync(0xffffffffu, l0, off);
                l1 += __shfl_xor_sync(0xffffffffu, l1, off);
                l2 += __shfl_xor_sync(0xffffffffu, l2, off);
                l3 += __shfl_xor_sync(0xffffffffu, l3, off);
            }
            if (lane == 0) {
                slog[4*warp + 0] = l0;
                slog[4*warp + 1] = l1;
                slog[4*warp + 2] = l2;
                slog[4*warp + 3] = l3;
            }
        }
        __syncthreads();

        if (warp == 0) {
            float logit = (lane < 20) ? slog[lane] : 0.f;
            {
                float mm = fmaxf(logit, __shfl_xor_sync(0xffffffffu, logit, 1));
                mm = fmaxf(mm, __shfl_xor_sync(0xffffffffu, mm, 2));
                float ex = __expf(logit - mm);
                float ttl = ex + __shfl_xor_sync(0xffffffffu, ex, 1);
                ttl += __shfl_xor_sync(0xffffffffu, ttl, 2);
                if (lane >= 16 && lane < 20) sstat[lane - 16] = ex / ttl;
            }
            int e = lane & 15, r = e >> 2, c = e & 3;
            float qoff = 0.f;
            if (lane < 16) {
                float x = logit;
                float sp = fmaxf(x, 0.f) + log1pf(__expf(-fabsf(x)));
                qoff = (r == c) ? 0.f : sp;
            }
            float s1 = qoff + __shfl_xor_sync(0xffffffffu, qoff, 1);
            float rs = s1 + __shfl_xor_sync(0xffffffffu, s1, 2);
            float Qown = (r == c) ? -rs : qoff;
            float Qe = __shfl_sync(0xffffffffu, Qown, lane & 15);

            int base = lane & 16;
            float bsc = ((lane < 16) ? bb1 : bb2) * 0.125f;
            float Av = Qe * bsc;
            float Ev = Av + ((r == c) ? 1.f : 0.f);
            float Tm = Av;
            #pragma unroll
            for (int n = 2; n <= 7; n++) {
                float s = 0.f;
                #pragma unroll
                for (int j = 0; j < 4; j++) {
                    float trj = __shfl_sync(0xffffffffu, Tm, base + (r<<2) + j);
                    float ajc = __shfl_sync(0xffffffffu, Av, base + (j<<2) + c);
                    s += trj * ajc;
                }
                Tm = s * (1.f / (float)n);
                Ev += Tm;
            }
            #pragma unroll
            for (int qq = 0; qq < 3; qq++) {
                float s = 0.f;
                #pragma unroll
                for (int j = 0; j < 4; j++) {
                    float erj = __shfl_sync(0xffffffffu, Ev, base + (r<<2) + j);
                    float ejc = __shfl_sync(0xffffffffu, Ev, base + (j<<2) + c);
                    s += erj * ejc;
                }
                Ev = s;
            }
            Ev = fmaxf(Ev, 1e-30f);
            if (lane < 16) { sP1[e] = Ev; g_P1[z*16 + e] = Ev; }
            else           { sP2[e] = Ev; g_P2[z*16 + e] = Ev; }
        }
        __syncthreads();
        {
            float tot = 0.f;
            #pragma unroll
            for (int a = 0; a < 4; a++) {
                float m1 = sP1[a*4+0]*e10 + sP1[a*4+1]*e11 + sP1[a*4+2]*e12 + sP1[a*4+3]*e13;
                float m2 = sP2[a*4+0]*e20 + sP2[a*4+1]*e21 + sP2[a*4+2]*e22 + sP2[a*4+3]*e23;
                tot += m1 * m2 * sstat[a];
            }
            float val = __logf(tot);
            #pragma unroll
            for (int off = 16; off; off >>= 1)
                val += __shfl_down_sync(0xffffffffu, val, off);
            if (lane == 0) s_red[warp] = val;
        }
        __syncthreads();
        if (tid == 0) {
            float s = 0.f;
            #pragma unroll
            for (int w = 0; w < 8; w++) s += s_red[w];
            g_llnew[z] = s;
            __threadfence();
            atomicAdd(&g_cnt[k], 1);
        }
    } else {
        // ----- selector block for particle k -----
        int k = blockIdx.x - (2*K_ + Z_);
        if (tid == 0) {
            while (*((volatile int*)&g_cnt[k]) < 6) __nanosleep(64);
            __threadfence();
        }
        __syncthreads();
        if (warp == 0) {
            int gk = indexes[k];
            float ck = g_ckept[k*T_ + lane];
            int l = lc[gk*T_ + lane];
            float fl = f_logdf(logdf, l);
            float cc = (l > 1) ? 1.f : 0.f;
            float sb = b1r[gk*R_ + lane] + b2r[gk*R_ + lane];
            #pragma unroll
            for (int off = 16; off; off >>= 1) {
                ck += __shfl_down_sync(0xffffffffu, ck, off);
                fl += __shfl_down_sync(0xffffffffu, fl, off);
                cc += __shfl_down_sync(0xffffffffu, cc, off);
                sb += __shfl_down_sync(0xffffffffu, sb, off);
            }
            float s_ct   = __shfl_sync(0xffffffffu, ck, 0);
            float s_flcT = __shfl_sync(0xffffffffu, fl, 0);
            float s_cT   = __shfl_sync(0xffffffffu, cc, 0);
            float s_sb   = __shfl_sync(0xffffffffu, sb, 0);

            float lw = -1e30f, lpn = 0.f, loglik = 0.f, gum = -1e30f;
            if (lane < J_) {
                int zc = k*J_ + lane;
                int c1 = idx1a[zc], c2 = idx2a[zc];
                loglik = s_ct - g_ckept[k*T_ + c1] - g_ckept[k*T_ + c2] + g_llnew[zc];
                float lbp = 2.f * (float)RP1 * LOG10F - 10.f * (s_sb + br1[zc] + br2[zc]);
                int l1 = lc[gk*T_ + c1], l2 = lc[gk*T_ + c2];
                float flcnew = s_flcT - f_logdf(logdf, l1) - f_logdf(logdf, l2)
                             + f_logdf(logdf, l1 + l2);
                float cnt = s_cT - (float)(l1 > 1) - (float)(l2 > 1) + 1.f;
                lpn = loglik + lbp - flcnew;
                lw = lpn - log_pi[gk] + __logf(cnt) - logvp[zc];
                gum = lw + gumbel[zc];
            }
            float m = lw;
            m = fmaxf(m, __shfl_xor_sync(0xffffffffu, m, 1));
            m = fmaxf(m, __shfl_xor_sync(0xffffffffu, m, 2));
            float ex = (lane < J_) ? __expf(lw - m) : 0.f;
            float se = ex + __shfl_xor_sync(0xffffffffu, ex, 1);
            se += __shfl_xor_sync(0xffffffffu, se, 2);

            float g0 = __shfl_sync(0xffffffffu, gum, 0);
            float g1 = __shfl_sync(0xffffffffu, gum, 1);
            float g2 = __shfl_sync(0xffffffffu, gum, 2);
            float g3 = __shfl_sync(0xffffffffu, gum, 3);
            int best = 0; float bv = g0;
            if (g1 > bv) { bv = g1; best = 1; }
            if (g2 > bv) { bv = g2; best = 2; }
            if (g3 > bv) { bv = g3; best = 3; }
            float lpn_b  = __shfl_sync(0xffffffffu, lpn, best);
            float llik_b = __shfl_sync(0xffffffffu, loglik, best);

            if (lane == 0) {
                int zs = k*J_ + best;
                g_selinfo[k] = make_int4(gk, idx1a[zs], idx2a[zs], zs);
                out[O10 + k] = m + __logf(se) - LOG4F;
                out[O9 + k]  = lpn_b;
                out[O11 + k] = llik_b;
                g_cnt[k] = 0;
            }
        }
    }
}

// ---------------- Kernel 2: outputs. grid (9, K), block 256 ----------------
// Plain writeback stores: output (18.5 MB) and lf (16.8 MB) both fit in L2;
// stores complete at LTS rate, DRAM drain is lazy. (__stcs was the R2-R12
// bottleneck: it forced stores to DRAM-write rate.)
__global__ void __launch_bounds__(256, 8) k2(
        const int* __restrict__ lc, const int* __restrict__ hashes,
        const float* __restrict__ embt, const float* __restrict__ lf,
        const float* __restrict__ embJ,
        const float* __restrict__ br1, const float* __restrict__ br2,
        const int* __restrict__ m1r, const int* __restrict__ m2r,
        const float* __restrict__ b1r, const float* __restrict__ b2r,
        const float* __restrict__ embr,
        float* __restrict__ out) {
    int i = blockIdx.x;
    int k = blockIdx.y;
    int tid = threadIdx.x;
    int4 si = g_selinfo[k];
    int gk = si.x, i1 = si.y, i2 = si.z, zs = si.w;
    int a = min(i1, i2), b = max(i1, i2);

    if (i < 7) {
        int nbase = 4*i;
        int tt[4];
        #pragma unroll
        for (int r = 0; r < 4; r++) {
            int t = nbase + r;
            if (t >= a) t++;
            if (t >= b) t++;
            tt[r] = t;
        }
        // batch all 4 loads (MLP=4), then 4 plain stores
        float4 v0 = ((const float4*)(lf + (size_t)(gk*T_ + tt[0])*S_*A_))[tid];
        float4 v1 = ((const float4*)(lf + (size_t)(gk*T_ + tt[1])*S_*A_))[tid];
        float4 v2 = ((const float4*)(lf + (size_t)(gk*T_ + tt[2])*S_*A_))[tid];
        float4 v3 = ((const float4*)(lf + (size_t)(gk*T_ + tt[3])*S_*A_))[tid];
        ((float4*)(out + O8 + (size_t)(k*TM1 + nbase + 0)*S_*A_))[tid] = v0;
        ((float4*)(out + O8 + (size_t)(k*TM1 + nbase + 1)*S_*A_))[tid] = v1;
        ((float4*)(out + O8 + (size_t)(k*TM1 + nbase + 2)*S_*A_))[tid] = v2;
        ((float4*)(out + O8 + (size_t)(k*TM1 + nbase + 3)*S_*A_))[tid] = v3;
        {
            int r = tid >> 6, d = tid & 63;
            out[O7 + (size_t)(k*TM1 + nbase + r)*D_ + d] =
                embt[(size_t)(gk*T_ + tt[r])*D_ + d];
        }
        if (tid < 4) {
            out[O5 + k*TM1 + nbase + tid] = (float)lc[gk*T_ + tt[tid]];
            out[O6 + k*TM1 + nbase + tid] = (float)hashes[gk*T_ + tt[tid]];
        }
    } else if (i == 7) {
        __shared__ float sP1[16], sP2[16];
        if (tid < 16) sP1[tid] = g_P1[zs*16 + tid];
        else if (tid < 32) sP2[tid-16] = g_P2[zs*16 + tid - 16];
        int t0 = 28; if (t0 >= a) t0++; if (t0 >= b) t0++;
        int t1 = 29; if (t1 >= a) t1++; if (t1 >= b) t1++;
        float4 v0 = ((const float4*)(lf + (size_t)(gk*T_ + t0)*S_*A_))[tid];
        float4 v1 = ((const float4*)(lf + (size_t)(gk*T_ + t1)*S_*A_))[tid];
        float4 w1 = ((const float4*)(lf + (size_t)(gk*T_ + i1)*S_*A_))[tid];
        float4 w2 = ((const float4*)(lf + (size_t)(gk*T_ + i2)*S_*A_))[tid];
        ((float4*)(out + O8 + (size_t)(k*TM1 + 28)*S_*A_))[tid] = v0;
        ((float4*)(out + O8 + (size_t)(k*TM1 + 29)*S_*A_))[tid] = v1;
        __syncthreads();
        {
            float e10=__expf(w1.x), e11=__expf(w1.y), e12=__expf(w1.z), e13=__expf(w1.w);
            float e20=__expf(w2.x), e21=__expf(w2.y), e22=__expf(w2.z), e23=__expf(w2.w);
            float4 res;
            float* rp = (float*)&res;
            #pragma unroll
            for (int aa = 0; aa < 4; aa++) {
                float m1 = sP1[aa*4+0]*e10 + sP1[aa*4+1]*e11 + sP1[aa*4+2]*e12 + sP1[aa*4+3]*e13;
                float m2 = sP2[aa*4+0]*e20 + sP2[aa*4+1]*e21 + sP2[aa*4+2]*e22 + sP2[aa*4+3]*e23;
                rp[aa] = __logf(m1) + __logf(m2);
            }
            ((float4*)(out + O8 + (size_t)(k*TM1 + 30)*S_*A_))[tid] = res;
        }
        if (tid < 192) {
            int r = tid >> 6, d = tid & 63;
            float val;
            if (r < 2) {
                int t = (r == 0) ? t0 : t1;
                val = embt[(size_t)(gk*T_ + t)*D_ + d];
            } else {
                val = embJ[(size_t)zs*D_ + d];
            }
            out[O7 + (size_t)(k*TM1 + 28 + r)*D_ + d] = val;
        }
        if (tid < 2) {
            int t = (tid == 0) ? t0 : t1;
            out[O5 + k*TM1 + 28 + tid] = (float)lc[gk*T_ + t];
            out[O6 + k*TM1 + 28 + tid] = (float)hashes[gk*T_ + t];
        } else if (tid == 2) {
            int l1 = lc[gk*T_ + i1], l2 = lc[gk*T_ + i2];
            out[O5 + k*TM1 + 30] = (float)(l1 + l2);
            int h1 = hashes[gk*T_ + i1], h2 = hashes[gk*T_ + i2];
            int mn = min(h1, h2), mx = max(h1, h2);
            unsigned int hh = ((unsigned int)mn * 1000003u + (unsigned int)mx) * 40503u + 2531011u;
            out[O6 + k*TM1 + 30] = (float)(int)hh;
        }
    } else {
        if (tid < RP1) {
            int r = tid;
            float v1, v2, vb1, vb2;
            if (r < R_) {
                v1 = (float)m1r[gk*R_ + r];
                v2 = (float)m2r[gk*R_ + r];
                vb1 = b1r[gk*R_ + r];
                vb2 = b2r[gk*R_ + r];
            } else {
                v1 = (float)i1; v2 = (float)i2;
                vb1 = br1[zs];  vb2 = br2[zs];
            }
            out[O0 + k*RP1 + r] = v1;
            out[O1 + k*RP1 + r] = v2;
            out[O2 + k*RP1 + r] = vb1;
            out[O3 + k*RP1 + r] = vb2;
        }
        const float4* s4 = (const float4*)(embr + (size_t)gk*R_*D_);
        float4* d4 = (float4*)(out + O4 + (size_t)k*RP1*D_);
        d4[tid] = s4[tid];
        d4[tid + 256] = s4[tid + 256];
        if (tid < 16) {
            const float4* j4 = (const float4*)(embJ + (size_t)zs*D_);
            d4[512 + tid] = j4[tid];
        }
    }
}

// ---------------- launch ----------------
extern "C" void kernel_launch(void* const* d_in, const int* in_sizes, int n_in,
                              void* d_out, int out_size) {
    const int*   indexes = (const int*)  d_in[0];
    const int*   m1r     = (const int*)  d_in[1];
    const int*   m2r     = (const int*)  d_in[2];
    const float* b1r     = (const float*)d_in[3];
    const float* b2r     = (const float*)d_in[4];
    const float* embr    = (const float*)d_in[5];
    const int*   lc      = (const int*)  d_in[6];
    const int*   hashes  = (const int*)  d_in[7];
    const float* embt    = (const float*)d_in[8];
    const float* lf      = (const float*)d_in[9];
    const float* log_pi  = (const float*)d_in[10];
    const int*   idx1a   = (const int*)  d_in[11];
    const int*   idx2a   = (const int*)  d_in[12];
    const float* br1     = (const float*)d_in[13];
    const float* br2     = (const float*)d_in[14];
    const float* embJ    = (const float*)d_in[15];
    const float* logvp   = (const float*)d_in[16];
    const float* gumbel  = (const float*)d_in[17];
    const float* Wq      = (const float*)d_in[18];
    const float* Wstat   = (const float*)d_in[19];
    const float* logdf   = (const float*)d_in[20];
    float* out = (float*)d_out;

    k1<<<2*K_ + Z_ + K_, 256>>>(indexes, lc, embt, lf, Wstat,
                                idx1a, idx2a, br1, br2, embJ, Wq,
                                b1r, b2r, log_pi, logvp, gumbel, logdf, out);
    k2<<<dim3(9, K_), 256>>>(lc, hashes, embt, lf, embJ, br1, br2,
                             m1r, m2r, b1r, b2r, embr, out);
}